// round 4
// baseline (speedup 1.0000x reference)
#include <cuda_runtime.h>

#define Bb 256
#define Tt 256
#define Hd 1024
#define Ee 256
#define LC 320
#define EIN 576   // E + L + C
#define G3 3072
#define Vv 64

#define GRID 136
#define NTHREADS 256

// ---------------- persistent device scratch ----------------
__device__ float g_ctxpart[Bb * G3];     // context @ W_ih[:,E:]^T + b_ih   [B][3H]
__device__ float g_table[Vv * G3];       // emb @ W_ih[:,:E]^T              [V][3H]
__device__ float g_h[2][Bb * Hd];        // ping-pong hidden state
__device__ unsigned g_count = 0;
__device__ unsigned g_phase = 0;

// ---------------- small helpers ----------------
__device__ __forceinline__ unsigned long long pk2(float x, float y) {
    unsigned long long r;
    asm("mov.b64 %0, {%1, %2};" : "=l"(r) : "f"(x), "f"(y));
    return r;
}
__device__ __forceinline__ float2 unpk(unsigned long long v) {
    float2 r;
    asm("mov.b64 {%0, %1}, %2;" : "=f"(r.x), "=f"(r.y) : "l"(v));
    return r;
}
// packed fp32x2 FMA (FFMA2) — 2x FFMA throughput on sm_103a
__device__ __forceinline__ void fma2(unsigned long long& d, unsigned long long a, unsigned long long b) {
    asm("fma.rn.f32x2 %0, %1, %2, %0;" : "+l"(d) : "l"(a), "l"(b));
}
__device__ __forceinline__ float sigm(float x) { return 1.f / (1.f + __expf(-x)); }
__device__ __forceinline__ float tanh_f(float x) { return 2.f / (1.f + __expf(-2.f * x)) - 1.f; }

// ---------------- grid barrier (sense via monotonic phase) ----------------
__device__ __forceinline__ void gbar(unsigned target) {
    __syncthreads();
    if (threadIdx.x == 0) {
        unsigned n;
        asm volatile("atom.add.acq_rel.gpu.u32 %0, [%1], 1;"
                     : "=r"(n) : "l"(&g_count) : "memory");
        if (n == GRID - 1) {
            g_count = 0;
            asm volatile("st.release.gpu.u32 [%0], %1;"
                         :: "l"(&g_phase), "r"(target) : "memory");
        } else {
            unsigned p;
            do {
                asm volatile("ld.acquire.gpu.u32 %0, [%1];"
                             : "=r"(p) : "l"(&g_phase) : "memory");
            } while ((int)(p - target) < 0);
        }
        // fence.gpu -> CCTL.IVALL: invalidate this SM's L1 so weak loads can't
        // hit lines cached before the barrier.
        __threadfence();
    }
    __syncthreads();
}

// ---------------- precompute kernels ----------------
// ctxpart[b][g] = sum_i ctx[b][i] * W_ih[g][E+i] + b_ih[g]
__global__ void ctx_kernel(const float* __restrict__ z, const float* __restrict__ c,
                           const float* __restrict__ Wih, const float* __restrict__ bih) {
    __shared__ float cs[8 * LC];
    int bc = blockIdx.x;  // 32 blocks, 8 batches each
    for (int i = threadIdx.x; i < 8 * LC; i += NTHREADS) {
        int bb = i / LC, ii = i - bb * LC;
        int b = bc * 8 + bb;
        cs[i] = (ii < 256) ? z[b * 256 + ii] : c[b * 64 + (ii - 256)];
    }
    __syncthreads();
    for (int gk = 0; gk < 12; gk++) {
        int g = threadIdx.x + gk * NTHREADS;
        float acc[8];
        float bi = bih[g];
#pragma unroll
        for (int bb = 0; bb < 8; bb++) acc[bb] = bi;
        const float* wr = Wih + (size_t)g * EIN + Ee;
        for (int ii = 0; ii < LC; ii++) {
            float w = wr[ii];
#pragma unroll
            for (int bb = 0; bb < 8; bb++) acc[bb] += w * cs[bb * LC + ii];
        }
#pragma unroll
        for (int bb = 0; bb < 8; bb++) g_ctxpart[(size_t)(bc * 8 + bb) * G3 + g] = acc[bb];
    }
}

// h0[b][j] = sum_i ctx[b][i] * W_fch[j][i] + b_fch[j]
__global__ void h0_kernel(const float* __restrict__ z, const float* __restrict__ c,
                          const float* __restrict__ Wfch, const float* __restrict__ bfch) {
    __shared__ float cs[8 * LC];
    int bc = blockIdx.x;
    for (int i = threadIdx.x; i < 8 * LC; i += NTHREADS) {
        int bb = i / LC, ii = i - bb * LC;
        int b = bc * 8 + bb;
        cs[i] = (ii < 256) ? z[b * 256 + ii] : c[b * 64 + (ii - 256)];
    }
    __syncthreads();
    for (int jk = 0; jk < 4; jk++) {
        int j = threadIdx.x + jk * NTHREADS;
        float acc[8];
        float bj = bfch[j];
#pragma unroll
        for (int bb = 0; bb < 8; bb++) acc[bb] = bj;
        const float* wr = Wfch + (size_t)j * LC;
        for (int ii = 0; ii < LC; ii++) {
            float w = wr[ii];
#pragma unroll
            for (int bb = 0; bb < 8; bb++) acc[bb] += w * cs[bb * LC + ii];
        }
#pragma unroll
        for (int bb = 0; bb < 8; bb++) g_h[0][(size_t)(bc * 8 + bb) * Hd + j] = acc[bb];
    }
}

// table[v][g] = sum_e emb[v][e] * W_ih[g][e]   (E = 256, tiled in 4 chunks of 64)
__global__ void table_kernel(const float* __restrict__ emb, const float* __restrict__ Wih) {
    __shared__ float es[Vv * 64];
    int g = blockIdx.x * NTHREADS + threadIdx.x;  // 12 blocks -> 3072 g's
    float acc[Vv];
#pragma unroll
    for (int v = 0; v < Vv; v++) acc[v] = 0.f;
    for (int ec = 0; ec < Ee / 64; ec++) {
        __syncthreads();
        for (int i = threadIdx.x; i < Vv * 64; i += NTHREADS) {
            int v = i >> 6, el = i & 63;
            es[i] = emb[(size_t)v * Ee + ec * 64 + el];
        }
        __syncthreads();
        const float* wr = Wih + (size_t)g * EIN + ec * 64;
#pragma unroll 8
        for (int e = 0; e < 64; e++) {
            float w = wr[e];
#pragma unroll
            for (int v = 0; v < Vv; v++) acc[v] += w * es[v * 64 + e];
        }
    }
    for (int v = 0; v < Vv; v++) g_table[(size_t)v * G3 + g] = acc[v];
}

// ---------------- persistent recurrent kernel ----------------
// 136 CTAs: CTAs 0..127 = gh tiles (64 b x 32 j x 3 gates, fused GRU epilogue)
//           CTAs 128..135 = logits tiles for the previous step (32 b x 64 v)
#define ASS 68    // a-tile smem row stride (floats)
#define WSS 100   // w-tile smem row stride
#define HSS 68    // logits smem strides
#define SMEM_FLOATS 6528

__device__ __forceinline__ void gh_tile(int bid, int t,
                                        const float* __restrict__ hcur, float* __restrict__ hnxt,
                                        const int* __restrict__ seq,
                                        const float* __restrict__ Whh, const float* __restrict__ bhh,
                                        float* sm) {
    float* as = sm;             // [16][ASS]  a[k][m] = h[b0+m][k0+k]
    float* ws = sm + 16 * ASS;  // [16][WSS]  w[k][n] (n = gate*32 + j)
    const int tid = threadIdx.x;
    const int tx = tid & 15, ty = tid >> 4;
    const int mt = bid & 3, jt = bid >> 2;
    const int b0 = mt * 64, j0 = jt * 32;

    unsigned long long acc[4][3];
#pragma unroll
    for (int i = 0; i < 4; i++)
#pragma unroll
        for (int q = 0; q < 3; q++) acc[i][q] = 0ull;

    const int arow = tid >> 2, akq = tid & 3;
    const float* aptr = hcur + (size_t)(b0 + arow) * Hd + akq * 4;
    const int wrow0 = tid >> 2, wkq0 = tid & 3;
    const int widx1 = 256 + tid;
    const int wrow1 = widx1 >> 2, wkq1 = widx1 & 3;
    const int g0 = (wrow0 >> 5) * Hd + j0 + (wrow0 & 31);
    const int g1 = (wrow1 >> 5) * Hd + j0 + (wrow1 & 31);
    const float* wptr0 = Whh + (size_t)g0 * Hd + wkq0 * 4;
    const float* wptr1 = Whh + (size_t)g1 * Hd + wkq1 * 4;

    // L2-only loads of the ping-pong hidden state (L1 may hold stale lines
    // from two steps ago; the grid barrier alone does not invalidate L1).
    float4 rA = __ldcg((const float4*)aptr);
    float4 rW0 = *(const float4*)(wptr0);
    float4 rW1 = make_float4(0.f, 0.f, 0.f, 0.f);
    if (tid < 128) rW1 = *(const float4*)(wptr1);

    for (int kt = 0; kt < 64; kt++) {
        __syncthreads();
        as[(akq * 4 + 0) * ASS + arow] = rA.x;
        as[(akq * 4 + 1) * ASS + arow] = rA.y;
        as[(akq * 4 + 2) * ASS + arow] = rA.z;
        as[(akq * 4 + 3) * ASS + arow] = rA.w;
        ws[(wkq0 * 4 + 0) * WSS + wrow0] = rW0.x;
        ws[(wkq0 * 4 + 1) * WSS + wrow0] = rW0.y;
        ws[(wkq0 * 4 + 2) * WSS + wrow0] = rW0.z;
        ws[(wkq0 * 4 + 3) * WSS + wrow0] = rW0.w;
        if (tid < 128) {
            ws[(wkq1 * 4 + 0) * WSS + wrow1] = rW1.x;
            ws[(wkq1 * 4 + 1) * WSS + wrow1] = rW1.y;
            ws[(wkq1 * 4 + 2) * WSS + wrow1] = rW1.z;
            ws[(wkq1 * 4 + 3) * WSS + wrow1] = rW1.w;
        }
        __syncthreads();
        if (kt < 63) {
            rA = __ldcg((const float4*)(aptr + (kt + 1) * 16));
            rW0 = *(const float4*)(wptr0 + (kt + 1) * 16);
            if (tid < 128) rW1 = *(const float4*)(wptr1 + (kt + 1) * 16);
        }
#pragma unroll
        for (int k = 0; k < 16; k++) {
            float4 av = *(const float4*)&as[k * ASS + ty * 4];
            unsigned long long a0 = pk2(av.x, av.x);
            unsigned long long a1 = pk2(av.y, av.y);
            unsigned long long a2 = pk2(av.z, av.z);
            unsigned long long a3 = pk2(av.w, av.w);
            unsigned long long bq0 = *(const unsigned long long*)&ws[k * WSS + 0 + tx * 2];
            unsigned long long bq1 = *(const unsigned long long*)&ws[k * WSS + 32 + tx * 2];
            unsigned long long bq2 = *(const unsigned long long*)&ws[k * WSS + 64 + tx * 2];
            fma2(acc[0][0], a0, bq0); fma2(acc[0][1], a0, bq1); fma2(acc[0][2], a0, bq2);
            fma2(acc[1][0], a1, bq0); fma2(acc[1][1], a1, bq1); fma2(acc[1][2], a1, bq2);
            fma2(acc[2][0], a2, bq0); fma2(acc[2][1], a2, bq1); fma2(acc[2][2], a2, bq2);
            fma2(acc[3][0], a3, bq0); fma2(acc[3][1], a3, bq1); fma2(acc[3][2], a3, bq2);
        }
    }

    // fused GRU gating epilogue
    const int j = j0 + tx * 2;
    const float2 br = *(const float2*)&bhh[j];
    const float2 bz = *(const float2*)&bhh[Hd + j];
    const float2 bn = *(const float2*)&bhh[2 * Hd + j];
#pragma unroll
    for (int im = 0; im < 4; im++) {
        int b = b0 + ty * 4 + im;
        int tok = seq[b * Tt + t];
        const float* tb = g_table + (size_t)tok * G3;
        const float* cp = g_ctxpart + (size_t)b * G3;
        float2 gr = unpk(acc[im][0]);
        float2 gz = unpk(acc[im][1]);
        float2 gn = unpk(acc[im][2]);
        float2 tr = *(const float2*)&tb[j];          float2 cr = *(const float2*)&cp[j];
        float2 tz = *(const float2*)&tb[Hd + j];     float2 cz = *(const float2*)&cp[Hd + j];
        float2 tn = *(const float2*)&tb[2 * Hd + j]; float2 cn = *(const float2*)&cp[2 * Hd + j];
        float2 ho = __ldcg((const float2*)&hcur[(size_t)b * Hd + j]);

        float r0 = sigm(tr.x + cr.x + gr.x + br.x);
        float u0 = sigm(tz.x + cz.x + gz.x + bz.x);
        float n0 = tanh_f(tn.x + cn.x + r0 * (gn.x + bn.x));
        float h0v = (1.f - u0) * n0 + u0 * ho.x;

        float r1 = sigm(tr.y + cr.y + gr.y + br.y);
        float u1 = sigm(tz.y + cz.y + gz.y + bz.y);
        float n1 = tanh_f(tn.y + cn.y + r1 * (gn.y + bn.y));
        float h1v = (1.f - u1) * n1 + u1 * ho.y;

        *(float2*)&hnxt[(size_t)b * Hd + j] = make_float2(h0v, h1v);
    }
}

__device__ __forceinline__ void logits_tile(int lb, int tout,
                                            const float* __restrict__ hcur,
                                            const float* __restrict__ Wout,
                                            const float* __restrict__ bout,
                                            float* __restrict__ out, float* sm) {
    float* hs = sm;             // [32][HSS]  h[b][k]
    float* wo = sm + 32 * HSS;  // [64][HSS]  w[k][v] (transposed)
    const int tid = threadIdx.x;
    const int b0 = lb * 32;
    const int bl = tid >> 3;   // 0..31
    const int vq = tid & 7;    // 8 v's per thread
    unsigned long long acc[4] = {0ull, 0ull, 0ull, 0ull};

    for (int kc = 0; kc < Hd; kc += 64) {
        __syncthreads();
        {
            int idx = tid, row = idx >> 4, kq = idx & 15;
            *(float4*)&hs[row * HSS + kq * 4] =
                __ldcg((const float4*)&hcur[(size_t)(b0 + row) * Hd + kc + kq * 4]);
            idx = tid + 256; row = idx >> 4; kq = idx & 15;
            *(float4*)&hs[row * HSS + kq * 4] =
                __ldcg((const float4*)&hcur[(size_t)(b0 + row) * Hd + kc + kq * 4]);
        }
#pragma unroll
        for (int i = 0; i < 4; i++) {
            int idx = tid + 256 * i;
            int v = idx >> 4, kq = idx & 15;
            float4 w = *(const float4*)&Wout[(size_t)v * Hd + kc + kq * 4];
            wo[(kq * 4 + 0) * HSS + v] = w.x;
            wo[(kq * 4 + 1) * HSS + v] = w.y;
            wo[(kq * 4 + 2) * HSS + v] = w.z;
            wo[(kq * 4 + 3) * HSS + v] = w.w;
        }
        __syncthreads();
#pragma unroll
        for (int k = 0; k < 64; k++) {
            float hv = hs[bl * HSS + k];
            unsigned long long hdp = pk2(hv, hv);
            const float* wr = &wo[k * HSS + vq * 8];
            fma2(acc[0], hdp, *(const unsigned long long*)&wr[0]);
            fma2(acc[1], hdp, *(const unsigned long long*)&wr[2]);
            fma2(acc[2], hdp, *(const unsigned long long*)&wr[4]);
            fma2(acc[3], hdp, *(const unsigned long long*)&wr[6]);
        }
    }
    int b = b0 + bl;
    float* op = out + ((size_t)b * Tt + tout) * Vv + vq * 8;
#pragma unroll
    for (int i = 0; i < 4; i++) {
        float2 v = unpk(acc[i]);
        float2 bo = *(const float2*)&bout[vq * 8 + i * 2];
        op[i * 2 + 0] = v.x + bo.x;
        op[i * 2 + 1] = v.y + bo.y;
    }
}

__global__ void __launch_bounds__(NTHREADS, 1)
gru_kernel(const int* __restrict__ seq, const float* __restrict__ Whh,
           const float* __restrict__ bhh, const float* __restrict__ Wout,
           const float* __restrict__ bout, float* __restrict__ out) {
    __shared__ float sm[SMEM_FLOATS];
    __shared__ unsigned base_s;
    if (threadIdx.x == 0) {
        unsigned p;
        asm volatile("ld.acquire.gpu.u32 %0, [%1];" : "=r"(p) : "l"(&g_phase) : "memory");
        base_s = p;
    }
    __syncthreads();
    const unsigned base = base_s;
    const int bid = blockIdx.x;

    for (int it = 0; it <= Tt; ++it) {
        const float* hcur = g_h[it & 1];
        float* hnxt = g_h[(it + 1) & 1];
        if (bid < 128) {
            if (it < Tt) gh_tile(bid, it, hcur, hnxt, seq, Whh, bhh, sm);
        } else {
            if (it >= 1) logits_tile(bid - 128, it - 1, hcur, Wout, bout, out, sm);
        }
        gbar(base + (unsigned)it + 1u);
    }
}

// ---------------- launch ----------------
extern "C" void kernel_launch(void* const* d_in, const int* in_sizes, int n_in,
                              void* d_out, int out_size) {
    (void)in_sizes; (void)n_in; (void)out_size;
    const float* z    = (const float*)d_in[0];
    const float* c    = (const float*)d_in[1];
    const int*   seq  = (const int*)  d_in[2];
    const float* emb  = (const float*)d_in[3];
    const float* Wfch = (const float*)d_in[4];
    const float* bfch = (const float*)d_in[5];
    const float* Wih  = (const float*)d_in[6];
    const float* bih  = (const float*)d_in[7];
    const float* Whh  = (const float*)d_in[8];
    const float* bhh  = (const float*)d_in[9];
    const float* Wout = (const float*)d_in[10];
    const float* bout = (const float*)d_in[11];
    float* out = (float*)d_out;

    ctx_kernel<<<32, NTHREADS>>>(z, c, Wih, bih);
    h0_kernel<<<32, NTHREADS>>>(z, c, Wfch, bfch);
    table_kernel<<<12, NTHREADS>>>(emb, Wih);
    gru_kernel<<<GRID, NTHREADS>>>(seq, Whh, bhh, Wout, bout, out);
}